// round 1
// baseline (speedup 1.0000x reference)
#include <cuda_runtime.h>

// Appro_WAConv2d: depthwise 7x7 conv with mantissa-approximation factor.
// Restructured as out = conv(u, A) + conv(v, B), where
//   u = x, v = x / M1(x), A = w / M2(w), B = w - A,
//   M(t) = (|t|+1e-7) normalized into [0.75, 1.5) (pure exponent manipulation).

#define Hc 56
#define Wc 56
#define Cc 192
#define Bc 4
#define KKc 49
#define PADV 3
#define TILE 62          // 56 + 2*3 halo
#define PITCH 65         // odd pitch -> lane==row accesses are bank-conflict-free
#define NTHREADS 224     // 7 warps: warp = x-strip (8 cols), lane = row

__device__ __forceinline__ float mant_map(float t) {
    // (|t|+eps) * 2^-n normalized into [0.75, 1.5)
    float a = fabsf(t) + 1e-7f;
    unsigned ai = __float_as_uint(a);
    float m = __uint_as_float((ai & 0x007FFFFFu) | 0x3F800000u);  // in [1,2)
    return (m >= 1.5f) ? m * 0.5f : m;                            // in [0.75,1.5)
}

__global__ __launch_bounds__(NTHREADS)
void waconv_kernel(const float* __restrict__ x,
                   const float* __restrict__ w,
                   float* __restrict__ out) {
    __shared__ float su[TILE * PITCH];
    __shared__ float sv[TILE * PITCH];
    __shared__ float sA[KKc];
    __shared__ float sB[KKc];

    const int bc  = blockIdx.x;       // b*C + c
    const int c   = bc % Cc;
    const int tid = threadIdx.x;

    // --- per-channel weight transform (49 values) ---
    if (tid < KKc) {
        float wv = w[c * KKc + tid];
        float M2 = mant_map(wv);
        float A  = wv / M2;
        sA[tid] = A;
        sB[tid] = wv - A;
    }

    // --- load input plane with halo; compute u and v = x/M1 on the fly ---
    const float* xp = x + (size_t)bc * (Hc * Wc);
    for (int i = tid; i < TILE * TILE; i += NTHREADS) {
        int r  = i / TILE;
        int cc = i - r * TILE;
        int gy = r - PADV;
        int gx = cc - PADV;
        float xv = 0.0f;
        if ((unsigned)gy < (unsigned)Hc && (unsigned)gx < (unsigned)Wc)
            xv = __ldg(xp + gy * Wc + gx);
        float M1 = mant_map(xv);
        su[r * PITCH + cc] = xv;
        sv[r * PITCH + cc] = __fdividef(xv, M1);   // 0 when xv==0 (M1 >= 0.75)
    }
    __syncthreads();

    // --- compute: each thread does an 8-wide x-strip, looping over rows ---
    const int strip = tid >> 5;   // 0..6
    const int lane  = tid & 31;   // row within pass
    const int x0    = strip * 8;
    float* op = out + (size_t)bc * (Hc * Wc);

    for (int y = lane; y < Hc; y += 32) {
        float acc[8];
        #pragma unroll
        for (int i = 0; i < 8; i++) acc[i] = 0.0f;

        #pragma unroll
        for (int ky = 0; ky < 7; ky++) {
            const float* ur = &su[(y + ky) * PITCH + x0];
            const float* vr = &sv[(y + ky) * PITCH + x0];
            float uu[14], vv[14];
            #pragma unroll
            for (int j = 0; j < 14; j++) { uu[j] = ur[j]; vv[j] = vr[j]; }

            #pragma unroll
            for (int kx = 0; kx < 7; kx++) {
                float wa = sA[ky * 7 + kx];
                float wb = sB[ky * 7 + kx];
                #pragma unroll
                for (int ox = 0; ox < 8; ox++) {
                    acc[ox] += uu[kx + ox] * wa;
                    acc[ox] += vv[kx + ox] * wb;
                }
            }
        }

        float4* o4 = (float4*)(op + y * Wc + x0);
        o4[0] = make_float4(acc[0], acc[1], acc[2], acc[3]);
        o4[1] = make_float4(acc[4], acc[5], acc[6], acc[7]);
    }
}

extern "C" void kernel_launch(void* const* d_in, const int* in_sizes, int n_in,
                              void* d_out, int out_size) {
    const float* x = (const float*)d_in[0];   // (4,192,56,56) f32
    const float* w = (const float*)d_in[1];   // (192,1,7,7)  f32
    float* out = (float*)d_out;               // (4,192,56,56) f32
    (void)in_sizes; (void)n_in; (void)out_size;
    waconv_kernel<<<Bc * Cc, NTHREADS>>>(x, w, out);
}

// round 2
// speedup vs baseline: 1.0906x; 1.0906x over previous
#include <cuda_runtime.h>

// Appro_WAConv2d: depthwise 7x7 conv with mantissa-approximation factor.
// Restructured as out = conv(u, A) + conv(v, B):
//   u = x, v = x / M1(x), A = w / M2(w), B = w - A,
//   M(t) = (|t|+1e-7) normalized into [0.75, 1.5).
// R2: (u,v) interleaved as float2 in shared; dual-stream FMA via fma.rn.f32x2
// (FFMA2) with packed weights (A,B) -> halves FMA and LDS instruction counts.

#define Hc 56
#define Wc 56
#define Cc 192
#define Bc 4
#define KKc 49
#define PADV 3
#define TILE 62          // 56 + 2*3 halo
#define PITCH2 63        // odd float2 pitch -> conflict-free LDS.64 across lanes
#define NTHREADS 224     // 7 warps: warp = x-strip (8 cols), lane = row

typedef unsigned long long u64;

__device__ __forceinline__ float mant_map(float t) {
    float a = fabsf(t) + 1e-7f;
    unsigned ai = __float_as_uint(a);
    float m = __uint_as_float((ai & 0x007FFFFFu) | 0x3F800000u);  // [1,2)
    return (m >= 1.5f) ? m * 0.5f : m;                            // [0.75,1.5)
}

__device__ __forceinline__ void ffma2(u64& d, u64 a, u64 b) {
    // d.lo += a.lo*b.lo ; d.hi += a.hi*b.hi   (packed dual fp32 FMA)
    asm("fma.rn.f32x2 %0, %1, %2, %0;" : "+l"(d) : "l"(a), "l"(b));
}

__global__ __launch_bounds__(NTHREADS)
void waconv_kernel(const float* __restrict__ x,
                   const float* __restrict__ w,
                   float* __restrict__ out) {
    __shared__ float2 suv[TILE * PITCH2];
    __shared__ float2 swab[KKc];

    const int bc  = blockIdx.x;       // b*C + c
    const int c   = bc % Cc;
    const int tid = threadIdx.x;

    // --- per-channel weight transform: packed (A, B) per tap ---
    if (tid < KKc) {
        float wv = w[c * KKc + tid];
        float M2 = mant_map(wv);
        float A  = wv / M2;
        swab[tid] = make_float2(A, wv - A);
    }

    // --- load plane with halo; build interleaved (u, v) tile ---
    const float* xp = x + (size_t)bc * (Hc * Wc);
    for (int i = tid; i < TILE * TILE; i += NTHREADS) {
        int r  = i / TILE;
        int cc = i - r * TILE;
        int gy = r - PADV;
        int gx = cc - PADV;
        float xv = 0.0f;
        if ((unsigned)gy < (unsigned)Hc && (unsigned)gx < (unsigned)Wc)
            xv = __ldg(xp + gy * Wc + gx);
        float M1 = mant_map(xv);
        suv[r * PITCH2 + cc] = make_float2(xv, __fdividef(xv, M1));
    }
    __syncthreads();

    // --- compute: each thread does an 8-wide x-strip per row iteration ---
    const int strip = tid >> 5;   // 0..6
    const int lane  = tid & 31;
    const int x0    = strip * 8;
    float* op = out + (size_t)bc * (Hc * Wc);

    for (int y = lane; y < Hc; y += 32) {
        u64 acc[8];
        #pragma unroll
        for (int i = 0; i < 8; i++) acc[i] = 0ull;   // (0.0f, 0.0f)

        #pragma unroll
        for (int ky = 0; ky < 7; ky++) {
            const u64* row = (const u64*)&suv[(y + ky) * PITCH2 + x0];
            u64 win[14];
            #pragma unroll
            for (int j = 0; j < 14; j++) win[j] = row[j];

            const u64* wrow = (const u64*)&swab[ky * 7];
            #pragma unroll
            for (int kx = 0; kx < 7; kx++) {
                u64 wp = wrow[kx];                    // broadcast (A, B)
                #pragma unroll
                for (int ox = 0; ox < 8; ox++)
                    ffma2(acc[ox], win[kx + ox], wp);
            }
        }

        // out = accU + accV
        float s[8];
        #pragma unroll
        for (int i = 0; i < 8; i++) {
            float lo, hi;
            asm("mov.b64 {%0, %1}, %2;" : "=f"(lo), "=f"(hi) : "l"(acc[i]));
            s[i] = lo + hi;
        }
        float4* o4 = (float4*)(op + y * Wc + x0);
        o4[0] = make_float4(s[0], s[1], s[2], s[3]);
        o4[1] = make_float4(s[4], s[5], s[6], s[7]);
    }
}

extern "C" void kernel_launch(void* const* d_in, const int* in_sizes, int n_in,
                              void* d_out, int out_size) {
    const float* x = (const float*)d_in[0];   // (4,192,56,56) f32
    const float* w = (const float*)d_in[1];   // (192,1,7,7)  f32
    float* out = (float*)d_out;               // (4,192,56,56) f32
    (void)in_sizes; (void)n_in; (void)out_size;
    waconv_kernel<<<Bc * Cc, NTHREADS>>>(x, w, out);
}

// round 6
// speedup vs baseline: 1.2896x; 1.1825x over previous
#include <cuda_runtime.h>

// Appro_WAConv2d: depthwise 7x7 conv with mantissa-approximation factor.
// out = conv(u, A) + conv(v, B):  u = x, v = x / M1(x), A = w / M2(w), B = w - A,
// M(t) = (|t|+1e-7) normalized into [0.75, 1.5).
// R2: dual-stream FFMA2 (fma.rn.f32x2) with (u,v) interleaved float2 in smem.
// R3: plane split into 2 y-halves (grid 1536, 1 y-iter/thread, smem 17KB),
//     constant-trip unrolled halo loader (MLP~10), launch_bounds(224,5).

#define Hc 56
#define Wc 56
#define Cc 192
#define Bc 4
#define KKc 49
#define PADV 3
#define HROWS 28               // output rows per CTA
#define TROWS (HROWS + 6)      // 34 tile rows incl. halo
#define TCOLS 62               // 56 + 2*3
#define PITCH2 63              // odd float2 pitch -> conflict-free LDS.64
#define NTHREADS 224           // 7 warps: warp = 8-col x-strip, lane = out row
#define NLOAD ((TROWS * TCOLS + NTHREADS - 1) / NTHREADS)   // 10

typedef unsigned long long u64;

__device__ __forceinline__ float mant_map(float t) {
    float a = fabsf(t) + 1e-7f;
    unsigned ai = __float_as_uint(a);
    float m = __uint_as_float((ai & 0x007FFFFFu) | 0x3F800000u);  // [1,2)
    return (m >= 1.5f) ? m * 0.5f : m;                            // [0.75,1.5)
}

__device__ __forceinline__ void ffma2(u64& d, u64 a, u64 b) {
    asm("fma.rn.f32x2 %0, %1, %2, %0;" : "+l"(d) : "l"(a), "l"(b));
}

__global__ __launch_bounds__(NTHREADS, 5)
void waconv_kernel(const float* __restrict__ x,
                   const float* __restrict__ w,
                   float* __restrict__ out) {
    __shared__ float2 suv[TROWS * PITCH2];
    __shared__ float2 swab[KKc];

    const int bc   = blockIdx.x >> 1;        // b*C + c
    const int half = blockIdx.x & 1;         // 0: rows 0..27, 1: rows 28..55
    const int c    = bc % Cc;
    const int tid  = threadIdx.x;
    const int y0   = half * HROWS;

    // --- per-channel weight transform: packed (A, B) per tap ---
    if (tid < KKc) {
        float wv = w[c * KKc + tid];
        float M2 = mant_map(wv);
        float A  = wv / M2;
        swab[tid] = make_float2(A, wv - A);
    }

    // --- halo load (rows y0-3 .. y0+30), fully unrolled for MLP ---
    const float* xp = x + (size_t)bc * (Hc * Wc);
    float xv[NLOAD];
    int   ridx[NLOAD];
    #pragma unroll
    for (int it = 0; it < NLOAD; it++) {
        int idx = tid + it * NTHREADS;
        int r   = idx / TCOLS;               // const-div -> mul/shift
        int cc  = idx - r * TCOLS;
        int gy  = y0 + r - PADV;
        int gx  = cc - PADV;
        float v = 0.0f;
        if (idx < TROWS * TCOLS &&
            (unsigned)gy < (unsigned)Hc && (unsigned)gx < (unsigned)Wc)
            v = __ldg(xp + gy * Wc + gx);
        xv[it]   = v;
        ridx[it] = r * PITCH2 + cc;
    }
    #pragma unroll
    for (int it = 0; it < NLOAD; it++) {
        int idx = tid + it * NTHREADS;
        if (idx < TROWS * TCOLS) {
            float v  = xv[it];
            float M1 = mant_map(v);
            suv[ridx[it]] = make_float2(v, __fdividef(v, M1));
        }
    }
    __syncthreads();

    // --- compute: thread = (8-col strip, 1 output row) ---
    const int strip = tid >> 5;              // 0..6
    const int lane  = tid & 31;              // local output row
    if (lane >= HROWS) return;
    const int x0 = strip * 8;

    u64 acc[8];
    #pragma unroll
    for (int i = 0; i < 8; i++) acc[i] = 0ull;

    #pragma unroll
    for (int ky = 0; ky < 7; ky++) {
        const u64* row = (const u64*)&suv[(lane + ky) * PITCH2 + x0];
        u64 win[14];
        #pragma unroll
        for (int j = 0; j < 14; j++) win[j] = row[j];

        const u64* wrow = (const u64*)&swab[ky * 7];
        #pragma unroll
        for (int kx = 0; kx < 7; kx++) {
            u64 wp = wrow[kx];               // broadcast (A, B)
            #pragma unroll
            for (int ox = 0; ox < 8; ox++)
                ffma2(acc[ox], win[kx + ox], wp);
        }
    }

    float s[8];
    #pragma unroll
    for (int i = 0; i < 8; i++) {
        float lo, hi;
        asm("mov.b64 {%0, %1}, %2;" : "=f"(lo), "=f"(hi) : "l"(acc[i]));
        s[i] = lo + hi;
    }
    float4* o4 = (float4*)(out + (size_t)bc * (Hc * Wc) + (y0 + lane) * Wc + x0);
    o4[0] = make_float4(s[0], s[1], s[2], s[3]);
    o4[1] = make_float4(s[4], s[5], s[6], s[7]);
}

extern "C" void kernel_launch(void* const* d_in, const int* in_sizes, int n_in,
                              void* d_out, int out_size) {
    const float* x = (const float*)d_in[0];   // (4,192,56,56) f32
    const float* w = (const float*)d_in[1];   // (192,1,7,7)  f32
    float* out = (float*)d_out;               // (4,192,56,56) f32
    (void)in_sizes; (void)n_in; (void)out_size;
    waconv_kernel<<<Bc * Cc * 2, NTHREADS>>>(x, w, out);
}